// round 1
// baseline (speedup 1.0000x reference)
#include <cuda_runtime.h>
#include <math.h>

#define MUL0 16
#define MUL1 8
#define DIM_F 40
#define NRB 16
#define NRD 64
#define W_NUMEL 576

#define THREADS 512
#define WARPS 16
#define GRID 592

struct __align__(16) WarpScratch {
    float h[NRD][4];       // post-silu, includes /sqrt(NRD); [d][edge]
    float emb[4][NRB];
    float x[4][DIM_F];
    float dot[4][MUL1];
    float sh1[4][4];
    float r[4];
    int   src[4];
    int   dst[4];
    float sum[4][DIM_F];
};  // 2800 bytes, 16B-divisible

#define W2_FLOATS (NRD * W_NUMEL)          // 36864
#define W1_FLOATS (NRB * NRD)              // 1024
#define SMEM_BYTES ((W2_FLOATS + W1_FLOATS) * 4 + WARPS * (int)sizeof(WarpScratch))

__device__ __forceinline__ float silu_f(float z) {
    return z / (1.0f + expf(-z));
}

__global__ void zero_kernel(float4* __restrict__ out, int n4) {
    int i = blockIdx.x * blockDim.x + threadIdx.x;
    if (i < n4) out[i] = make_float4(0.f, 0.f, 0.f, 0.f);
}

__global__ __launch_bounds__(THREADS, 1)
void conv_kernel(const float* __restrict__ pos,
                 const float* __restrict__ f_in,
                 const int*   __restrict__ edge_src,
                 const int*   __restrict__ edge_dst,
                 const float* __restrict__ W1,
                 const float* __restrict__ W2,
                 float* __restrict__ f_out,
                 int n_edges)
{
    extern __shared__ float smem[];
    float* W2s = smem;
    float* W1s = smem + W2_FLOATS;
    WarpScratch* wsArr = reinterpret_cast<WarpScratch*>(smem + W2_FLOATS + W1_FLOATS);

    const int tid = threadIdx.x;

    // Stage weights in SMEM
    {
        const float4* src4 = reinterpret_cast<const float4*>(W2);
        float4* dst4 = reinterpret_cast<float4*>(W2s);
        for (int i = tid; i < W2_FLOATS / 4; i += THREADS) dst4[i] = src4[i];
        for (int i = tid; i < W1_FLOATS; i += THREADS) W1s[i] = W1[i];
    }
    __syncthreads();

    const int warp = tid >> 5;
    const int lane = tid & 31;
    WarpScratch* ws = &wsArr[warp];

    const int n_groups = n_edges >> 2;          // 4 edges per group
    const int gw = blockIdx.x * WARPS + warp;
    const int nw = gridDim.x * WARPS;

    for (int g = gw; g < n_groups; g += nw) {
        __syncwarp();
        // ---- Phase A: per-edge geometry (lanes 0..3) ----
        if (lane < 4) {
            int e = g * 4 + lane;
            int es = edge_src[e], ed = edge_dst[e];
            float ax = pos[es * 3 + 0], ay = pos[es * 3 + 1], az = pos[es * 3 + 2];
            float bx = pos[ed * 3 + 0], by = pos[ed * 3 + 1], bz = pos[ed * 3 + 2];
            float dx = bx - ax, dy = by - ay, dz = bz - az;
            float r = sqrtf(dx * dx + dy * dy + dz * dz + 1e-12f);
            float inv = 1.7320508075688772f / r;   // sqrt(3)/r
            ws->src[lane] = es;
            ws->dst[lane] = ed;
            ws->r[lane] = r;
            ws->sh1[lane][0] = dx * inv;
            ws->sh1[lane][1] = dy * inv;
            ws->sh1[lane][2] = dz * inv;
        }
        __syncwarp();
        // ---- Phase B: radial embedding (bump basis), 64 values ----
        {
            int i = lane & 15;
            float v = (5.0f / 17.0f) * (float)(i + 1);
            const float stepi = 17.0f / 5.0f;
            #pragma unroll
            for (int p = 0; p < 2; p++) {
                int k = (lane >> 4) + 2 * p;
                float r = ws->r[k];
                float d = (r - v) * stepi;
                float y = 0.0f;
                if (fabsf(d) < 1.0f) {
                    // 1.14136 * e^2 * exp(-1/(1+d)) * exp(-1/(1-d)) * sqrt(16)
                    y = 4.56544f * expf(2.0f - 1.0f / (1.0f + d) - 1.0f / (1.0f - d));
                }
                ws->emb[k][i] = y;
            }
        }
        __syncwarp();
        // ---- Phase C: h = silu(emb @ W1 / 4) / 8, stored [d][edge] ----
        {
            #pragma unroll
            for (int p = 0; p < 2; p++) {
                int d = lane + 32 * p;
                float z0 = 0.f, z1 = 0.f, z2 = 0.f, z3 = 0.f;
                #pragma unroll
                for (int i = 0; i < NRB; i++) {
                    float wv = W1s[i * NRD + d];
                    z0 += ws->emb[0][i] * wv;
                    z1 += ws->emb[1][i] * wv;
                    z2 += ws->emb[2][i] * wv;
                    z3 += ws->emb[3][i] * wv;
                }
                float4 hh;
                hh.x = silu_f(z0 * 0.25f) * 0.125f;
                hh.y = silu_f(z1 * 0.25f) * 0.125f;
                hh.z = silu_f(z2 * 0.25f) * 0.125f;
                hh.w = silu_f(z3 * 0.25f) * 0.125f;
                *reinterpret_cast<float4*>(ws->h[d]) = hh;
            }
        }
        // ---- Phase D: gather x = f_in[src], zero summand ----
        {
            #pragma unroll
            for (int t = 0; t < 5; t++) {
                int idx = lane + 32 * t;          // 0..159
                int k = idx / DIM_F;
                int c = idx - k * DIM_F;
                ws->x[k][c] = f_in[ws->src[k] * DIM_F + c];
                ws->sum[k][c] = 0.0f;
            }
        }
        __syncwarp();
        // ---- Phase D2: dot[u] = x1[u,:] . sh1 ----
        {
            int k = lane >> 3, u = lane & 7;
            float s = ws->x[k][16 + u * 3 + 0] * ws->sh1[k][0]
                    + ws->x[k][16 + u * 3 + 1] * ws->sh1[k][1]
                    + ws->x[k][16 + u * 3 + 2] * ws->sh1[k][2];
            ws->dot[k][u] = s;
        }
        __syncwarp();
        // ---- Phase E: GEMV  w = h @ W2  (packed f32x2, 4 edges) ----
        unsigned long long acc01[18], acc23[18];
        #pragma unroll
        for (int j = 0; j < 18; j++) { acc01[j] = 0ULL; acc23[j] = 0ULL; }
        {
            const float* w2p = W2s + lane;
            #pragma unroll 4
            for (int d = 0; d < NRD; d++) {
                ulonglong2 hp = *reinterpret_cast<const ulonglong2*>(ws->h[d]);
                const float* row = w2p + d * W_NUMEL;
                #pragma unroll
                for (int j = 0; j < 18; j++) {
                    float wv = row[32 * j];
                    unsigned long long wp;
                    asm("mov.b64 %0, {%1, %1};" : "=l"(wp) : "f"(wv));
                    asm("fma.rn.f32x2 %0, %1, %2, %0;" : "+l"(acc01[j]) : "l"(hp.x), "l"(wp));
                    asm("fma.rn.f32x2 %0, %1, %2, %0;" : "+l"(acc23[j]) : "l"(hp.y), "l"(wp));
                }
            }
        }
        // ---- Phase F: tensor product -> summand (SMEM atomics) ----
        {
            const float inv_s3 = 0.57735026918962576f;
            #pragma unroll
            for (int j = 0; j < 18; j++) {
                int c = lane + 32 * j;
                float wk[4];
                asm("mov.b64 {%0, %1}, %2;" : "=f"(wk[0]), "=f"(wk[1]) : "l"(acc01[j]));
                asm("mov.b64 {%0, %1}, %2;" : "=f"(wk[2]), "=f"(wk[3]) : "l"(acc23[j]));
                if (c < 256) {                       // w00[u,v] * x0[u] -> out0[v]
                    int u = c >> 4, v = c & 15;
                    #pragma unroll
                    for (int k = 0; k < 4; k++)
                        atomicAdd(&ws->sum[k][v], wk[k] * ws->x[k][u]);
                } else if (c < 384) {                // w01[u,wp] * x0[u] * sh1[kk] -> out1[wp,kk]
                    int idx = c - 256;
                    int u = idx >> 3, wp = idx & 7;
                    #pragma unroll
                    for (int k = 0; k < 4; k++) {
                        float cf = wk[k] * ws->x[k][u];
                        atomicAdd(&ws->sum[k][16 + wp * 3 + 0], cf * ws->sh1[k][0]);
                        atomicAdd(&ws->sum[k][16 + wp * 3 + 1], cf * ws->sh1[k][1]);
                        atomicAdd(&ws->sum[k][16 + wp * 3 + 2], cf * ws->sh1[k][2]);
                    }
                } else if (c < 448) {                // w10[u,wp] * x1[u,kk] -> out1[wp,kk]
                    int idx = c - 384;
                    int u = idx >> 3, wp = idx & 7;
                    #pragma unroll
                    for (int k = 0; k < 4; k++) {
                        atomicAdd(&ws->sum[k][16 + wp * 3 + 0], wk[k] * ws->x[k][16 + u * 3 + 0]);
                        atomicAdd(&ws->sum[k][16 + wp * 3 + 1], wk[k] * ws->x[k][16 + u * 3 + 1]);
                        atomicAdd(&ws->sum[k][16 + wp * 3 + 2], wk[k] * ws->x[k][16 + u * 3 + 2]);
                    }
                } else {                             // w11[u,v] * dot[u] * inv_s3 -> out0[v]
                    int idx = c - 448;
                    int u = idx >> 4, v = idx & 15;
                    #pragma unroll
                    for (int k = 0; k < 4; k++)
                        atomicAdd(&ws->sum[k][v], inv_s3 * wk[k] * ws->dot[k][u]);
                }
            }
        }
        __syncwarp();
        // ---- Phase G: global scatter-add ----
        {
            const float s = 0.05103103630798288f;   // 1/(sqrt(24) * sqrt(16))
            #pragma unroll
            for (int t = 0; t < 5; t++) {
                int idx = lane + 32 * t;
                int k = idx / DIM_F;
                int c = idx - k * DIM_F;
                atomicAdd(&f_out[ws->dst[k] * DIM_F + c], ws->sum[k][c] * s);
            }
        }
    }
}

extern "C" void kernel_launch(void* const* d_in, const int* in_sizes, int n_in,
                              void* d_out, int out_size) {
    const float* pos  = (const float*)d_in[0];
    const float* f_in = (const float*)d_in[1];
    const int*   esrc = (const int*)d_in[2];
    const int*   edst = (const int*)d_in[3];
    const float* W1   = (const float*)d_in[4];
    const float* W2   = (const float*)d_in[5];
    float* out = (float*)d_out;
    int n_edges = in_sizes[2];

    cudaFuncSetAttribute(conv_kernel, cudaFuncAttributeMaxDynamicSharedMemorySize, SMEM_BYTES);

    int n4 = out_size / 4;
    zero_kernel<<<(n4 + 255) / 256, 256>>>((float4*)out, n4);
    conv_kernel<<<GRID, THREADS, SMEM_BYTES>>>(pos, f_in, esrc, edst, W1, W2, out, n_edges);
}